// round 10
// baseline (speedup 1.0000x reference)
#include <cuda_runtime.h>
#include <math.h>
#include <stdint.h>

// Problem dims
#define BATCH 128
#define SEQ   512
#define IDIM  1024
#define HDIM  1024
#define ODIM  1024
#define BH    (BATCH*HDIM)   // 131072
#define M1    (BATCH*SEQ)    // 65536
#define REC_BLOCKS 128

typedef unsigned long long u64;

// ---------------- scratch (static device memory; allocation-free) ----------
__device__ float g_pre[(size_t)SEQ*4*BATCH*HDIM]; // [t][g][b][j]   1 GiB
__device__ float g_hbuf[(size_t)SEQ*BATCH*HDIM];  // [t][b][j]      256 MiB
__device__ float g_c[BH];
__device__ float g_n[BH];
__device__ float g_m[BH];
// recurrent weights split to tf32 hi/lo, layout [128 blocks][32 n][1024 k]
__device__ uint32_t g_whi[(size_t)4096*1024];     // 16 MiB
__device__ uint32_t g_wlo[(size_t)4096*1024];     // 16 MiB

__device__ unsigned int g_cnt = 0;
__device__ unsigned int g_gen = 0;

// ---------------- tf32 helpers ---------------------------------------------
__device__ __forceinline__ uint32_t f2tf32(float f) {
    uint32_t r;
    asm("cvt.rna.tf32.f32 %0, %1;" : "=r"(r) : "f"(f));
    return r;
}
__device__ __forceinline__ void tf32_split(float v, uint32_t &hi, uint32_t &lo) {
    hi = f2tf32(v);
    float r = v - __uint_as_float(hi);
    lo = f2tf32(r);
}
__device__ __forceinline__ void mma_tf32(float* c, const uint32_t* a,
                                         uint32_t b0, uint32_t b1) {
    asm("mma.sync.aligned.m16n8k8.row.col.f32.tf32.tf32.f32 "
        "{%0,%1,%2,%3}, {%4,%5,%6,%7}, {%8,%9}, {%0,%1,%2,%3};"
        : "+f"(c[0]), "+f"(c[1]), "+f"(c[2]), "+f"(c[3])
        : "r"(a[0]), "r"(a[1]), "r"(a[2]), "r"(a[3]), "r"(b0), "r"(b1));
}

// ============================================================================
// 3xTF32 mma.sync GEMM (MODE 0: x @ Wg[:I] + bg -> g_pre,
//                       MODE 1: hbuf @ Wout + bout -> out)    [R7, passing]
// ============================================================================
struct MSmem {
    uint32_t Ah[2][16][136];
    uint32_t Al[2][16][136];
    uint32_t Bh[2][16][136];
    uint32_t Bl[2][16][136];
};
#define MSMEM_BYTES ((int)sizeof(MSmem))   // 69632

template <int MODE>
__global__ __launch_bounds__(256, 2) void k_mma(
    const float* __restrict__ Ag,
    const float* __restrict__ W0, const float* __restrict__ W1,
    const float* __restrict__ W2, const float* __restrict__ W3,
    const float* __restrict__ b0p, const float* __restrict__ b1p,
    const float* __restrict__ b2p, const float* __restrict__ b3p,
    float* __restrict__ dst)
{
    extern __shared__ char smem_raw[];
    MSmem* sm = (MSmem*)smem_raw;

    const int tid  = threadIdx.x;
    const int wid  = tid >> 5;
    const int lane = tid & 31;
    const int gr   = lane >> 2;
    const int cq   = lane & 3;

    const int z = (MODE == 0) ? blockIdx.z : 0;
    const float* W    = (z == 0) ? W0 : (z == 1) ? W1 : (z == 2) ? W2 : W3;
    const float* bias = (z == 0) ? b0p : (z == 1) ? b1p : (z == 2) ? b2p : b3p;
    const float* A    = (MODE == 0) ? Ag : (const float*)g_hbuf;

    const int n0 = blockIdx.x * 128;
    const int m0 = blockIdx.y * 128;

    const int warp_m = (wid & 3) * 32;
    const int warp_n = (wid >> 2) * 64;

    const int arow = tid >> 1;
    const int akof = (tid & 1) * 8;
    const float* aptr = A + (size_t)(m0 + arow) * 1024 + akof;

    const int bcol = (tid & 31) * 4;
    const int brow = (tid >> 5) * 2;
    const float* bptr = W + (size_t)brow * 1024 + n0 + bcol;

    float acc[2][8][4];
#pragma unroll
    for (int mt = 0; mt < 2; mt++)
#pragma unroll
        for (int nt = 0; nt < 8; nt++)
#pragma unroll
            for (int q = 0; q < 4; q++) acc[mt][nt][q] = 0.f;

#define LOAD_TILE(kb, st)                                                     \
    {                                                                         \
        float av[8];                                                          \
        *(float4*)&av[0] = *(const float4*)(aptr + (kb) * 16);                \
        *(float4*)&av[4] = *(const float4*)(aptr + (kb) * 16 + 4);            \
        _Pragma("unroll")                                                     \
        for (int q = 0; q < 8; q++) {                                         \
            uint32_t hi, lo;                                                  \
            tf32_split(av[q], hi, lo);                                        \
            sm->Ah[st][akof + q][arow] = hi;                                  \
            sm->Al[st][akof + q][arow] = lo;                                  \
        }                                                                     \
        float4 w0 = *(const float4*)(bptr + (size_t)(kb) * 16 * 1024);        \
        float4 w1 = *(const float4*)(bptr + (size_t)((kb) * 16 + 1) * 1024);  \
        uint4 h0, l0, h1, l1;                                                 \
        tf32_split(w0.x, h0.x, l0.x); tf32_split(w0.y, h0.y, l0.y);           \
        tf32_split(w0.z, h0.z, l0.z); tf32_split(w0.w, h0.w, l0.w);           \
        tf32_split(w1.x, h1.x, l1.x); tf32_split(w1.y, h1.y, l1.y);           \
        tf32_split(w1.z, h1.z, l1.z); tf32_split(w1.w, h1.w, l1.w);           \
        *(uint4*)&sm->Bh[st][brow][bcol]     = h0;                            \
        *(uint4*)&sm->Bl[st][brow][bcol]     = l0;                            \
        *(uint4*)&sm->Bh[st][brow + 1][bcol] = h1;                            \
        *(uint4*)&sm->Bl[st][brow + 1][bcol] = l1;                            \
    }

    LOAD_TILE(0, 0);

    for (int kb = 0; kb < 64; kb++) {
        const int st = kb & 1;
        __syncthreads();
        if (kb < 63) LOAD_TILE(kb + 1, st ^ 1);

#pragma unroll
        for (int kt = 0; kt < 2; kt++) {
            uint32_t ah[2][4], al[2][4];
#pragma unroll
            for (int mt = 0; mt < 2; mt++) {
                const int r = warp_m + mt * 16 + gr;
                ah[mt][0] = sm->Ah[st][kt * 8 + cq][r];
                ah[mt][1] = sm->Ah[st][kt * 8 + cq][r + 8];
                ah[mt][2] = sm->Ah[st][kt * 8 + cq + 4][r];
                ah[mt][3] = sm->Ah[st][kt * 8 + cq + 4][r + 8];
                al[mt][0] = sm->Al[st][kt * 8 + cq][r];
                al[mt][1] = sm->Al[st][kt * 8 + cq][r + 8];
                al[mt][2] = sm->Al[st][kt * 8 + cq + 4][r];
                al[mt][3] = sm->Al[st][kt * 8 + cq + 4][r + 8];
            }
#pragma unroll
            for (int nt = 0; nt < 8; nt++) {
                const int cn = warp_n + nt * 8 + gr;
                uint32_t bh0 = sm->Bh[st][kt * 8 + cq][cn];
                uint32_t bh1 = sm->Bh[st][kt * 8 + cq + 4][cn];
                uint32_t bl0 = sm->Bl[st][kt * 8 + cq][cn];
                uint32_t bl1 = sm->Bl[st][kt * 8 + cq + 4][cn];
                mma_tf32(acc[0][nt], al[0], bh0, bh1);
                mma_tf32(acc[0][nt], ah[0], bl0, bl1);
                mma_tf32(acc[0][nt], ah[0], bh0, bh1);
                mma_tf32(acc[1][nt], al[1], bh0, bh1);
                mma_tf32(acc[1][nt], ah[1], bl0, bl1);
                mma_tf32(acc[1][nt], ah[1], bh0, bh1);
            }
        }
    }
#undef LOAD_TILE

#pragma unroll
    for (int mt = 0; mt < 2; mt++) {
#pragma unroll
        for (int nt = 0; nt < 8; nt++) {
            const int col = n0 + warp_n + nt * 8 + 2 * cq;
            float2 bv = *(const float2*)(bias + col);
            const int r0 = m0 + warp_m + mt * 16 + gr;
            const int r1 = r0 + 8;
            float2 o0, o1;
            o0.x = acc[mt][nt][0] + bv.x; o0.y = acc[mt][nt][1] + bv.y;
            o1.x = acc[mt][nt][2] + bv.x; o1.y = acc[mt][nt][3] + bv.y;
            if (MODE == 0) {
                int b0i = r0 >> 9, t0i = r0 & 511;
                int b1i = r1 >> 9, t1i = r1 & 511;
                *(float2*)(g_pre + (((size_t)t0i * 4 + z) * BATCH + b0i) * HDIM + col) = o0;
                *(float2*)(g_pre + (((size_t)t1i * 4 + z) * BATCH + b1i) * HDIM + col) = o1;
            } else {
                int t0i = r0 >> 7, b0i = r0 & 127;
                int t1i = r1 >> 7, b1i = r1 & 127;
                *(float2*)(dst + ((size_t)b0i * SEQ + t0i) * ODIM + col) = o0;
                *(float2*)(dst + ((size_t)b1i * SEQ + t1i) * ODIM + col) = o1;
            }
        }
    }
}

// ============================================================================
// prep: split recurrent weights into tf32 hi/lo, layout [blk][32 n][1024 k]
// n-local = g*8 + jl ; global j = blk*8 + jl
// ============================================================================
__global__ __launch_bounds__(256) void k_split(
    const float* __restrict__ Wf, const float* __restrict__ Wi,
    const float* __restrict__ Wc, const float* __restrict__ Wo)
{
    const int np = blockIdx.x;                  // 0..4095
    const int k  = blockIdx.y * 256 + threadIdx.x;
    const int blk = np >> 5, loc = np & 31;
    const int g = loc >> 3, jl = loc & 7;
    const int j = blk * 8 + jl;
    const float* W = (g == 0) ? Wf : (g == 1) ? Wi : (g == 2) ? Wc : Wo;
    float v = W[(size_t)(IDIM + k) * HDIM + j];
    uint32_t hi, lo;
    tf32_split(v, hi, lo);
    g_whi[(size_t)np * 1024 + k] = hi;
    g_wlo[(size_t)np * 1024 + k] = lo;
}

// ============================================================================
// Persistent 3xTF32 recurrence: 128 CTAs (1/SM), 256 threads (8 warps).
// CTA owns 8 j-cols x 4 gates (N=32), all 128 batch rows. Per step:
// GEMM M=128,N=32,K=1024 (BK=32, double-buffered hi/lo smem), acc -> Gbuf,
// CTA-local pointwise with register-resident c/n/m, 1 grid barrier/step.
// ============================================================================
struct R2Smem {
    uint32_t Ah[2][128][36];   // [stage][m][k]  18432 B/stage
    uint32_t Al[2][128][36];
    uint32_t Bh[2][32][36];    // [stage][n][k]  4608 B/stage
    uint32_t Bl[2][32][36];
    float    Gbuf[128][36];    // gate sums [b][n]
};
#define R2SMEM_BYTES ((int)sizeof(R2Smem))   // ~110 KB

__device__ __forceinline__ void grid_barrier() {
    __threadfence();
    __syncthreads();
    if (threadIdx.x == 0) {
        unsigned int gen = *(volatile unsigned int*)&g_gen;
        unsigned int old = atomicAdd(&g_cnt, 1u);
        if (old == REC_BLOCKS - 1) {
            g_cnt = 0;
            __threadfence();
            atomicAdd(&g_gen, 1u);
        } else {
            while (*(volatile unsigned int*)&g_gen == gen) __nanosleep(64);
        }
        __threadfence();
    }
    __syncthreads();
}

__global__ __launch_bounds__(256, 1) void k_recur2() {
    extern __shared__ char smem_raw[];
    R2Smem* sm = (R2Smem*)smem_raw;

    const int tid  = threadIdx.x;
    const int wid  = tid >> 5;
    const int lane = tid & 31;
    const int gr   = lane >> 2;
    const int cq   = lane & 3;
    const int bid  = blockIdx.x;       // 0..127
    const int j0   = bid * 8;

    const int warp_m = (wid & 3) * 32;
    const int warp_n = (wid >> 2) * 16;

    // A loader: row = tid>>1, k-offset (tid&1)*16 (16 floats per thread/tile)
    const int arow = tid >> 1;
    const int akof = (tid & 1) * 16;
    // B loader: n = tid>>3, k-offset (tid&7)*4
    const int bn   = tid >> 3;
    const int bkof = (tid & 7) * 4;
    const uint32_t* whi = g_whi + (size_t)bid * 32 * 1024;
    const uint32_t* wlo = g_wlo + (size_t)bid * 32 * 1024;

    // pointwise: thread owns (b = tid>>1, jl = (tid&1)*4 + e), e = 0..3
    const int pb = tid >> 1;
    const int pj = (tid & 1) * 4;

    float cS[4] = {0.f, 0.f, 0.f, 0.f};
    float nS[4] = {0.f, 0.f, 0.f, 0.f};
    float mS[4] = {0.f, 0.f, 0.f, 0.f};

#define RLOADA(kb, st)                                                        \
    {                                                                         \
        const float* ap = Abase + (size_t)arow * 1024 + (kb) * 32 + akof;     \
        _Pragma("unroll")                                                     \
        for (int q = 0; q < 4; q++) {                                         \
            float4 v = *(const float4*)(ap + q * 4);                          \
            uint4 h, l;                                                       \
            tf32_split(v.x, h.x, l.x); tf32_split(v.y, h.y, l.y);             \
            tf32_split(v.z, h.z, l.z); tf32_split(v.w, h.w, l.w);             \
            *(uint4*)&sm->Ah[st][arow][akof + q * 4] = h;                     \
            *(uint4*)&sm->Al[st][arow][akof + q * 4] = l;                     \
        }                                                                     \
    }
#define RLOADB(kb, st)                                                        \
    {                                                                         \
        uint4 h = *(const uint4*)(whi + (size_t)bn * 1024 + (kb) * 32 + bkof);\
        uint4 l = *(const uint4*)(wlo + (size_t)bn * 1024 + (kb) * 32 + bkof);\
        *(uint4*)&sm->Bh[st][bn][bkof] = h;                                   \
        *(uint4*)&sm->Bl[st][bn][bkof] = l;                                   \
    }

    for (int t = 0; t < SEQ; t++) {
        float acc[2][2][4];
#pragma unroll
        for (int mt = 0; mt < 2; mt++)
#pragma unroll
            for (int nt = 0; nt < 2; nt++)
#pragma unroll
                for (int q = 0; q < 4; q++) acc[mt][nt][q] = 0.f;

        if (t > 0) {
            const float* Abase = g_hbuf + (size_t)(t - 1) * BH;
            RLOADA(0, 0);
            RLOADB(0, 0);

            for (int kb = 0; kb < 32; kb++) {
                const int st = kb & 1;
                __syncthreads();
                if (kb < 31) { RLOADA(kb + 1, st ^ 1); RLOADB(kb + 1, st ^ 1); }

#pragma unroll
                for (int kt = 0; kt < 4; kt++) {
                    uint32_t ah[2][4], al[2][4];
#pragma unroll
                    for (int mt = 0; mt < 2; mt++) {
                        const int r = warp_m + mt * 16 + gr;
                        ah[mt][0] = sm->Ah[st][r][kt * 8 + cq];
                        ah[mt][1] = sm->Ah[st][r + 8][kt * 8 + cq];
                        ah[mt][2] = sm->Ah[st][r][kt * 8 + cq + 4];
                        ah[mt][3] = sm->Ah[st][r + 8][kt * 8 + cq + 4];
                        al[mt][0] = sm->Al[st][r][kt * 8 + cq];
                        al[mt][1] = sm->Al[st][r + 8][kt * 8 + cq];
                        al[mt][2] = sm->Al[st][r][kt * 8 + cq + 4];
                        al[mt][3] = sm->Al[st][r + 8][kt * 8 + cq + 4];
                    }
#pragma unroll
                    for (int nt = 0; nt < 2; nt++) {
                        const int cn = warp_n + nt * 8 + gr;
                        uint32_t bh0 = sm->Bh[st][cn][kt * 8 + cq];
                        uint32_t bh1 = sm->Bh[st][cn][kt * 8 + cq + 4];
                        uint32_t bl0 = sm->Bl[st][cn][kt * 8 + cq];
                        uint32_t bl1 = sm->Bl[st][cn][kt * 8 + cq + 4];
                        mma_tf32(acc[0][nt], al[0], bh0, bh1);
                        mma_tf32(acc[0][nt], ah[0], bl0, bl1);
                        mma_tf32(acc[0][nt], ah[0], bh0, bh1);
                        mma_tf32(acc[1][nt], al[1], bh0, bh1);
                        mma_tf32(acc[1][nt], ah[1], bl0, bl1);
                        mma_tf32(acc[1][nt], ah[1], bh0, bh1);
                    }
                }
            }

            // store gate sums to Gbuf
            __syncthreads();
#pragma unroll
            for (int mt = 0; mt < 2; mt++) {
#pragma unroll
                for (int nt = 0; nt < 2; nt++) {
                    const int r0  = warp_m + mt * 16 + gr;
                    const int col = warp_n + nt * 8 + 2 * cq;
                    sm->Gbuf[r0][col]         = acc[mt][nt][0];
                    sm->Gbuf[r0][col + 1]     = acc[mt][nt][1];
                    sm->Gbuf[r0 + 8][col]     = acc[mt][nt][2];
                    sm->Gbuf[r0 + 8][col + 1] = acc[mt][nt][3];
                }
            }
            __syncthreads();
        }

        // ---- pointwise (CTA-local, state in registers) ----
        {
            const float* preb = g_pre + (size_t)t * 4 * BH;
            float* hout = g_hbuf + (size_t)t * BH + (size_t)pb * HDIM + j0;
#pragma unroll
            for (int e = 0; e < 4; e++) {
                const int jl = pj + e;
                float fl, il, cl, ol;
                fl = __ldg(preb + (size_t)0 * BH + (size_t)pb * HDIM + j0 + jl);
                il = __ldg(preb + (size_t)1 * BH + (size_t)pb * HDIM + j0 + jl);
                cl = __ldg(preb + (size_t)2 * BH + (size_t)pb * HDIM + j0 + jl);
                ol = __ldg(preb + (size_t)3 * BH + (size_t)pb * HDIM + j0 + jl);
                if (t > 0) {
                    fl += sm->Gbuf[pb][0 * 8 + jl];
                    il += sm->Gbuf[pb][1 * 8 + jl];
                    cl += sm->Gbuf[pb][2 * 8 + jl];
                    ol += sm->Gbuf[pb][3 * 8 + jl];
                }
                float mn = fmaxf(fl + mS[e], il);
                float it = __expf(il - mn);
                float ft = __expf(fl + mS[e] - mn);
                float ch = tanhf(cl);
                float ot = 1.f / (1.f + __expf(-ol));

                float cn = ft * cS[e] + it * ch;
                float nn = ft * nS[e] + it;
                float hn = ot * (cn / (nn + 1e-8f));

                cS[e] = cn; nS[e] = nn; mS[e] = mn;
                hout[jl] = hn;
            }
        }

        grid_barrier();   // h_t visible before any CTA reads it at t+1
    }

#undef RLOADA
#undef RLOADB

    // final state
#pragma unroll
    for (int e = 0; e < 4; e++) {
        const int idx = pb * HDIM + j0 + pj + e;
        g_c[idx] = cS[e];
        g_n[idx] = nS[e];
        g_m[idx] = mS[e];
    }
}

// ---------------- tail: final h, c, n, m -----------------------------------
__global__ __launch_bounds__(256) void k_tail(float* __restrict__ out) {
    int i = blockIdx.x * blockDim.x + threadIdx.x;
    int which = i / BH;
    int r = i - which * BH;
    float v;
    if (which == 0)      v = g_hbuf[(size_t)(SEQ - 1) * BH + r];
    else if (which == 1) v = g_c[r];
    else if (which == 2) v = g_n[r];
    else                 v = g_m[r];
    out[(size_t)M1 * ODIM + i] = v;
}

// ---------------- launch ----------------------------------------------------
extern "C" void kernel_launch(void* const* d_in, const int* in_sizes, int n_in,
                              void* d_out, int out_size) {
    const float* x    = (const float*)d_in[0];
    const float* Wf   = (const float*)d_in[1];
    const float* bf   = (const float*)d_in[2];
    const float* Wi   = (const float*)d_in[3];
    const float* bi   = (const float*)d_in[4];
    const float* Wc   = (const float*)d_in[5];
    const float* bc   = (const float*)d_in[6];
    const float* Wo   = (const float*)d_in[7];
    const float* bo   = (const float*)d_in[8];
    const float* Wout = (const float*)d_in[9];
    const float* bout = (const float*)d_in[10];
    float* out = (float*)d_out;

    static int attr_done = 0;
    if (!attr_done) {
        cudaFuncSetAttribute(k_mma<0>, cudaFuncAttributeMaxDynamicSharedMemorySize, MSMEM_BYTES);
        cudaFuncSetAttribute(k_mma<1>, cudaFuncAttributeMaxDynamicSharedMemorySize, MSMEM_BYTES);
        cudaFuncSetAttribute(k_recur2, cudaFuncAttributeMaxDynamicSharedMemorySize, R2SMEM_BYTES);
        attr_done = 1;
    }

    // prep: split recurrent weights into tf32 hi/lo (blocked layout)
    k_split<<<dim3(4096, 4), 256>>>(Wf, Wi, Wc, Wo);

    // phase 1 (3xTF32 mma.sync): pre[t][g][b][:] = x @ Wg[:I] + bg
    k_mma<0><<<dim3(8, 512, 4), 256, MSMEM_BYTES>>>(
        x, Wf, Wi, Wc, Wo, bf, bi, bc, bo, nullptr);

    // recurrence (3xTF32 mma.sync, persistent, 1 CTA/SM)
    k_recur2<<<REC_BLOCKS, 256, R2SMEM_BYTES>>>();

    // output projection (3xTF32 mma.sync): out = hbuf @ Wout + bout
    k_mma<1><<<dim3(8, 512, 1), 256, MSMEM_BYTES>>>(
        nullptr, Wout, Wout, Wout, Wout, bout, bout, bout, bout, out);

    // final h, c, n, m
    k_tail<<<(4 * BH) / 256, 256>>>(out);
}

// round 11
// speedup vs baseline: 1.0021x; 1.0021x over previous
#include <cuda_runtime.h>
#include <math.h>
#include <stdint.h>

// Problem dims
#define BATCH 128
#define SEQ   512
#define IDIM  1024
#define HDIM  1024
#define ODIM  1024
#define BH    (BATCH*HDIM)   // 131072
#define M1    (BATCH*SEQ)    // 65536
#define REC_BLOCKS 128

typedef unsigned long long u64;

// ---------------- scratch (static device memory; allocation-free) ----------
__device__ float g_pre[(size_t)SEQ*4*BATCH*HDIM]; // [t][g][b][j]   1 GiB
__device__ float g_hbuf[(size_t)SEQ*BATCH*HDIM];  // [t][b][j]      256 MiB
__device__ float g_c[BH];
__device__ float g_n[BH];
__device__ float g_m[BH];
// recurrent weights split to tf32 hi/lo, layout [128 blocks][32 n][1024 k]
__device__ uint32_t g_whi[(size_t)4096*1024];     // 16 MiB
__device__ uint32_t g_wlo[(size_t)4096*1024];     // 16 MiB

__device__ unsigned int g_cnt = 0;
__device__ unsigned int g_gen = 0;

// ---------------- tf32 helpers ---------------------------------------------
__device__ __forceinline__ uint32_t f2tf32(float f) {
    uint32_t r;
    asm("cvt.rna.tf32.f32 %0, %1;" : "=r"(r) : "f"(f));
    return r;
}
__device__ __forceinline__ void tf32_split(float v, uint32_t &hi, uint32_t &lo) {
    hi = f2tf32(v);
    float r = v - __uint_as_float(hi);
    lo = f2tf32(r);
}
__device__ __forceinline__ void mma_tf32(float* c, const uint32_t* a,
                                         uint32_t b0, uint32_t b1) {
    asm("mma.sync.aligned.m16n8k8.row.col.f32.tf32.tf32.f32 "
        "{%0,%1,%2,%3}, {%4,%5,%6,%7}, {%8,%9}, {%0,%1,%2,%3};"
        : "+f"(c[0]), "+f"(c[1]), "+f"(c[2]), "+f"(c[3])
        : "r"(a[0]), "r"(a[1]), "r"(a[2]), "r"(a[3]), "r"(b0), "r"(b1));
}

// ============================================================================
// 3xTF32 mma.sync GEMM (MODE 0: x @ Wg[:I] + bg -> g_pre,
//                       MODE 1: hbuf @ Wout + bout -> out)    [R7, passing]
// ============================================================================
struct MSmem {
    uint32_t Ah[2][16][136];
    uint32_t Al[2][16][136];
    uint32_t Bh[2][16][136];
    uint32_t Bl[2][16][136];
};
#define MSMEM_BYTES ((int)sizeof(MSmem))   // 69632

template <int MODE>
__global__ __launch_bounds__(256, 2) void k_mma(
    const float* __restrict__ Ag,
    const float* __restrict__ W0, const float* __restrict__ W1,
    const float* __restrict__ W2, const float* __restrict__ W3,
    const float* __restrict__ b0p, const float* __restrict__ b1p,
    const float* __restrict__ b2p, const float* __restrict__ b3p,
    float* __restrict__ dst)
{
    extern __shared__ char smem_raw[];
    MSmem* sm = (MSmem*)smem_raw;

    const int tid  = threadIdx.x;
    const int wid  = tid >> 5;
    const int lane = tid & 31;
    const int gr   = lane >> 2;
    const int cq   = lane & 3;

    const int z = (MODE == 0) ? blockIdx.z : 0;
    const float* W    = (z == 0) ? W0 : (z == 1) ? W1 : (z == 2) ? W2 : W3;
    const float* bias = (z == 0) ? b0p : (z == 1) ? b1p : (z == 2) ? b2p : b3p;
    const float* A    = (MODE == 0) ? Ag : (const float*)g_hbuf;

    const int n0 = blockIdx.x * 128;
    const int m0 = blockIdx.y * 128;

    const int warp_m = (wid & 3) * 32;
    const int warp_n = (wid >> 2) * 64;

    const int arow = tid >> 1;
    const int akof = (tid & 1) * 8;
    const float* aptr = A + (size_t)(m0 + arow) * 1024 + akof;

    const int bcol = (tid & 31) * 4;
    const int brow = (tid >> 5) * 2;
    const float* bptr = W + (size_t)brow * 1024 + n0 + bcol;

    float acc[2][8][4];
#pragma unroll
    for (int mt = 0; mt < 2; mt++)
#pragma unroll
        for (int nt = 0; nt < 8; nt++)
#pragma unroll
            for (int q = 0; q < 4; q++) acc[mt][nt][q] = 0.f;

#define LOAD_TILE(kb, st)                                                     \
    {                                                                         \
        float av[8];                                                          \
        *(float4*)&av[0] = *(const float4*)(aptr + (kb) * 16);                \
        *(float4*)&av[4] = *(const float4*)(aptr + (kb) * 16 + 4);            \
        _Pragma("unroll")                                                     \
        for (int q = 0; q < 8; q++) {                                         \
            uint32_t hi, lo;                                                  \
            tf32_split(av[q], hi, lo);                                        \
            sm->Ah[st][akof + q][arow] = hi;                                  \
            sm->Al[st][akof + q][arow] = lo;                                  \
        }                                                                     \
        float4 w0 = *(const float4*)(bptr + (size_t)(kb) * 16 * 1024);        \
        float4 w1 = *(const float4*)(bptr + (size_t)((kb) * 16 + 1) * 1024);  \
        uint4 h0, l0, h1, l1;                                                 \
        tf32_split(w0.x, h0.x, l0.x); tf32_split(w0.y, h0.y, l0.y);           \
        tf32_split(w0.z, h0.z, l0.z); tf32_split(w0.w, h0.w, l0.w);           \
        tf32_split(w1.x, h1.x, l1.x); tf32_split(w1.y, h1.y, l1.y);           \
        tf32_split(w1.z, h1.z, l1.z); tf32_split(w1.w, h1.w, l1.w);           \
        *(uint4*)&sm->Bh[st][brow][bcol]     = h0;                            \
        *(uint4*)&sm->Bl[st][brow][bcol]     = l0;                            \
        *(uint4*)&sm->Bh[st][brow + 1][bcol] = h1;                            \
        *(uint4*)&sm->Bl[st][brow + 1][bcol] = l1;                            \
    }

    LOAD_TILE(0, 0);

    for (int kb = 0; kb < 64; kb++) {
        const int st = kb & 1;
        __syncthreads();
        if (kb < 63) LOAD_TILE(kb + 1, st ^ 1);

#pragma unroll
        for (int kt = 0; kt < 2; kt++) {
            uint32_t ah[2][4], al[2][4];
#pragma unroll
            for (int mt = 0; mt < 2; mt++) {
                const int r = warp_m + mt * 16 + gr;
                ah[mt][0] = sm->Ah[st][kt * 8 + cq][r];
                ah[mt][1] = sm->Ah[st][kt * 8 + cq][r + 8];
                ah[mt][2] = sm->Ah[st][kt * 8 + cq + 4][r];
                ah[mt][3] = sm->Ah[st][kt * 8 + cq + 4][r + 8];
                al[mt][0] = sm->Al[st][kt * 8 + cq][r];
                al[mt][1] = sm->Al[st][kt * 8 + cq][r + 8];
                al[mt][2] = sm->Al[st][kt * 8 + cq + 4][r];
                al[mt][3] = sm->Al[st][kt * 8 + cq + 4][r + 8];
            }
#pragma unroll
            for (int nt = 0; nt < 8; nt++) {
                const int cn = warp_n + nt * 8 + gr;
                uint32_t bh0 = sm->Bh[st][kt * 8 + cq][cn];
                uint32_t bh1 = sm->Bh[st][kt * 8 + cq + 4][cn];
                uint32_t bl0 = sm->Bl[st][kt * 8 + cq][cn];
                uint32_t bl1 = sm->Bl[st][kt * 8 + cq + 4][cn];
                mma_tf32(acc[0][nt], al[0], bh0, bh1);
                mma_tf32(acc[0][nt], ah[0], bl0, bl1);
                mma_tf32(acc[0][nt], ah[0], bh0, bh1);
                mma_tf32(acc[1][nt], al[1], bh0, bh1);
                mma_tf32(acc[1][nt], ah[1], bl0, bl1);
                mma_tf32(acc[1][nt], ah[1], bh0, bh1);
            }
        }
    }
#undef LOAD_TILE

#pragma unroll
    for (int mt = 0; mt < 2; mt++) {
#pragma unroll
        for (int nt = 0; nt < 8; nt++) {
            const int col = n0 + warp_n + nt * 8 + 2 * cq;
            float2 bv = *(const float2*)(bias + col);
            const int r0 = m0 + warp_m + mt * 16 + gr;
            const int r1 = r0 + 8;
            float2 o0, o1;
            o0.x = acc[mt][nt][0] + bv.x; o0.y = acc[mt][nt][1] + bv.y;
            o1.x = acc[mt][nt][2] + bv.x; o1.y = acc[mt][nt][3] + bv.y;
            if (MODE == 0) {
                int b0i = r0 >> 9, t0i = r0 & 511;
                int b1i = r1 >> 9, t1i = r1 & 511;
                *(float2*)(g_pre + (((size_t)t0i * 4 + z) * BATCH + b0i) * HDIM + col) = o0;
                *(float2*)(g_pre + (((size_t)t1i * 4 + z) * BATCH + b1i) * HDIM + col) = o1;
            } else {
                int t0i = r0 >> 7, b0i = r0 & 127;
                int t1i = r1 >> 7, b1i = r1 & 127;
                *(float2*)(dst + ((size_t)b0i * SEQ + t0i) * ODIM + col) = o0;
                *(float2*)(dst + ((size_t)b1i * SEQ + t1i) * ODIM + col) = o1;
            }
        }
    }
}

// ============================================================================
// prep: split recurrent weights into tf32 hi/lo, layout [blk][32 n][1024 k]
// n-local = g*8 + jl ; global j = blk*8 + jl
// ============================================================================
__global__ __launch_bounds__(256) void k_split(
    const float* __restrict__ Wf, const float* __restrict__ Wi,
    const float* __restrict__ Wc, const float* __restrict__ Wo)
{
    const int np = blockIdx.x;                  // 0..4095
    const int k  = blockIdx.y * 256 + threadIdx.x;
    const int blk = np >> 5, loc = np & 31;
    const int g = loc >> 3, jl = loc & 7;
    const int j = blk * 8 + jl;
    const float* W = (g == 0) ? Wf : (g == 1) ? Wi : (g == 2) ? Wc : Wo;
    float v = W[(size_t)(IDIM + k) * HDIM + j];
    uint32_t hi, lo;
    tf32_split(v, hi, lo);
    g_whi[(size_t)np * 1024 + k] = hi;
    g_wlo[(size_t)np * 1024 + k] = lo;
}

// ============================================================================
// Persistent 3xTF32 recurrence: 128 CTAs (1/SM), 256 threads (8 warps).
// CTA owns 8 j-cols x 4 gates (N=32), all 128 batch rows. Per step:
// GEMM M=128,N=32,K=1024 (BK=32, double-buffered hi/lo smem), acc -> Gbuf,
// CTA-local pointwise with register-resident c/n/m, 1 grid barrier/step.
// ============================================================================
struct R2Smem {
    uint32_t Ah[2][128][36];   // [stage][m][k]  18432 B/stage
    uint32_t Al[2][128][36];
    uint32_t Bh[2][32][36];    // [stage][n][k]  4608 B/stage
    uint32_t Bl[2][32][36];
    float    Gbuf[128][36];    // gate sums [b][n]
};
#define R2SMEM_BYTES ((int)sizeof(R2Smem))   // ~110 KB

__device__ __forceinline__ void grid_barrier() {
    __threadfence();
    __syncthreads();
    if (threadIdx.x == 0) {
        unsigned int gen = *(volatile unsigned int*)&g_gen;
        unsigned int old = atomicAdd(&g_cnt, 1u);
        if (old == REC_BLOCKS - 1) {
            g_cnt = 0;
            __threadfence();
            atomicAdd(&g_gen, 1u);
        } else {
            while (*(volatile unsigned int*)&g_gen == gen) __nanosleep(64);
        }
        __threadfence();
    }
    __syncthreads();
}

__global__ __launch_bounds__(256, 1) void k_recur2() {
    extern __shared__ char smem_raw[];
    R2Smem* sm = (R2Smem*)smem_raw;

    const int tid  = threadIdx.x;
    const int wid  = tid >> 5;
    const int lane = tid & 31;
    const int gr   = lane >> 2;
    const int cq   = lane & 3;
    const int bid  = blockIdx.x;       // 0..127
    const int j0   = bid * 8;

    const int warp_m = (wid & 3) * 32;
    const int warp_n = (wid >> 2) * 16;

    // A loader: row = tid>>1, k-offset (tid&1)*16 (16 floats per thread/tile)
    const int arow = tid >> 1;
    const int akof = (tid & 1) * 16;
    // B loader: n = tid>>3, k-offset (tid&7)*4
    const int bn   = tid >> 3;
    const int bkof = (tid & 7) * 4;
    const uint32_t* whi = g_whi + (size_t)bid * 32 * 1024;
    const uint32_t* wlo = g_wlo + (size_t)bid * 32 * 1024;

    // pointwise: thread owns (b = tid>>1, jl = (tid&1)*4 + e), e = 0..3
    const int pb = tid >> 1;
    const int pj = (tid & 1) * 4;

    float cS[4] = {0.f, 0.f, 0.f, 0.f};
    float nS[4] = {0.f, 0.f, 0.f, 0.f};
    float mS[4] = {0.f, 0.f, 0.f, 0.f};

#define RLOADA(kb, st)                                                        \
    {                                                                         \
        const float* ap = Abase + (size_t)arow * 1024 + (kb) * 32 + akof;     \
        _Pragma("unroll")                                                     \
        for (int q = 0; q < 4; q++) {                                         \
            float4 v = *(const float4*)(ap + q * 4);                          \
            uint4 h, l;                                                       \
            tf32_split(v.x, h.x, l.x); tf32_split(v.y, h.y, l.y);             \
            tf32_split(v.z, h.z, l.z); tf32_split(v.w, h.w, l.w);             \
            *(uint4*)&sm->Ah[st][arow][akof + q * 4] = h;                     \
            *(uint4*)&sm->Al[st][arow][akof + q * 4] = l;                     \
        }                                                                     \
    }
#define RLOADB(kb, st)                                                        \
    {                                                                         \
        uint4 h = *(const uint4*)(whi + (size_t)bn * 1024 + (kb) * 32 + bkof);\
        uint4 l = *(const uint4*)(wlo + (size_t)bn * 1024 + (kb) * 32 + bkof);\
        *(uint4*)&sm->Bh[st][bn][bkof] = h;                                   \
        *(uint4*)&sm->Bl[st][bn][bkof] = l;                                   \
    }

    for (int t = 0; t < SEQ; t++) {
        float acc[2][2][4];
#pragma unroll
        for (int mt = 0; mt < 2; mt++)
#pragma unroll
            for (int nt = 0; nt < 2; nt++)
#pragma unroll
                for (int q = 0; q < 4; q++) acc[mt][nt][q] = 0.f;

        if (t > 0) {
            const float* Abase = g_hbuf + (size_t)(t - 1) * BH;
            RLOADA(0, 0);
            RLOADB(0, 0);

            for (int kb = 0; kb < 32; kb++) {
                const int st = kb & 1;
                __syncthreads();
                if (kb < 31) { RLOADA(kb + 1, st ^ 1); RLOADB(kb + 1, st ^ 1); }

#pragma unroll
                for (int kt = 0; kt < 4; kt++) {
                    uint32_t ah[2][4], al[2][4];
#pragma unroll
                    for (int mt = 0; mt < 2; mt++) {
                        const int r = warp_m + mt * 16 + gr;
                        ah[mt][0] = sm->Ah[st][r][kt * 8 + cq];
                        ah[mt][1] = sm->Ah[st][r + 8][kt * 8 + cq];
                        ah[mt][2] = sm->Ah[st][r][kt * 8 + cq + 4];
                        ah[mt][3] = sm->Ah[st][r + 8][kt * 8 + cq + 4];
                        al[mt][0] = sm->Al[st][r][kt * 8 + cq];
                        al[mt][1] = sm->Al[st][r + 8][kt * 8 + cq];
                        al[mt][2] = sm->Al[st][r][kt * 8 + cq + 4];
                        al[mt][3] = sm->Al[st][r + 8][kt * 8 + cq + 4];
                    }
#pragma unroll
                    for (int nt = 0; nt < 2; nt++) {
                        const int cn = warp_n + nt * 8 + gr;
                        uint32_t bh0 = sm->Bh[st][cn][kt * 8 + cq];
                        uint32_t bh1 = sm->Bh[st][cn][kt * 8 + cq + 4];
                        uint32_t bl0 = sm->Bl[st][cn][kt * 8 + cq];
                        uint32_t bl1 = sm->Bl[st][cn][kt * 8 + cq + 4];
                        mma_tf32(acc[0][nt], al[0], bh0, bh1);
                        mma_tf32(acc[0][nt], ah[0], bl0, bl1);
                        mma_tf32(acc[0][nt], ah[0], bh0, bh1);
                        mma_tf32(acc[1][nt], al[1], bh0, bh1);
                        mma_tf32(acc[1][nt], ah[1], bl0, bl1);
                        mma_tf32(acc[1][nt], ah[1], bh0, bh1);
                    }
                }
            }

            // store gate sums to Gbuf
            __syncthreads();
#pragma unroll
            for (int mt = 0; mt < 2; mt++) {
#pragma unroll
                for (int nt = 0; nt < 2; nt++) {
                    const int r0  = warp_m + mt * 16 + gr;
                    const int col = warp_n + nt * 8 + 2 * cq;
                    sm->Gbuf[r0][col]         = acc[mt][nt][0];
                    sm->Gbuf[r0][col + 1]     = acc[mt][nt][1];
                    sm->Gbuf[r0 + 8][col]     = acc[mt][nt][2];
                    sm->Gbuf[r0 + 8][col + 1] = acc[mt][nt][3];
                }
            }
            __syncthreads();
        }

        // ---- pointwise (CTA-local, state in registers) ----
        {
            const float* preb = g_pre + (size_t)t * 4 * BH;
            float* hout = g_hbuf + (size_t)t * BH + (size_t)pb * HDIM + j0;
#pragma unroll
            for (int e = 0; e < 4; e++) {
                const int jl = pj + e;
                float fl, il, cl, ol;
                fl = __ldg(preb + (size_t)0 * BH + (size_t)pb * HDIM + j0 + jl);
                il = __ldg(preb + (size_t)1 * BH + (size_t)pb * HDIM + j0 + jl);
                cl = __ldg(preb + (size_t)2 * BH + (size_t)pb * HDIM + j0 + jl);
                ol = __ldg(preb + (size_t)3 * BH + (size_t)pb * HDIM + j0 + jl);
                if (t > 0) {
                    fl += sm->Gbuf[pb][0 * 8 + jl];
                    il += sm->Gbuf[pb][1 * 8 + jl];
                    cl += sm->Gbuf[pb][2 * 8 + jl];
                    ol += sm->Gbuf[pb][3 * 8 + jl];
                }
                float mn = fmaxf(fl + mS[e], il);
                float it = __expf(il - mn);
                float ft = __expf(fl + mS[e] - mn);
                float ch = tanhf(cl);
                float ot = 1.f / (1.f + __expf(-ol));

                float cn = ft * cS[e] + it * ch;
                float nn = ft * nS[e] + it;
                float hn = ot * (cn / (nn + 1e-8f));

                cS[e] = cn; nS[e] = nn; mS[e] = mn;
                hout[jl] = hn;
            }
        }

        grid_barrier();   // h_t visible before any CTA reads it at t+1
    }

#undef RLOADA
#undef RLOADB

    // final state
#pragma unroll
    for (int e = 0; e < 4; e++) {
        const int idx = pb * HDIM + j0 + pj + e;
        g_c[idx] = cS[e];
        g_n[idx] = nS[e];
        g_m[idx] = mS[e];
    }
}

// ---------------- tail: final h, c, n, m -----------------------------------
__global__ __launch_bounds__(256) void k_tail(float* __restrict__ out) {
    int i = blockIdx.x * blockDim.x + threadIdx.x;
    int which = i / BH;
    int r = i - which * BH;
    float v;
    if (which == 0)      v = g_hbuf[(size_t)(SEQ - 1) * BH + r];
    else if (which == 1) v = g_c[r];
    else if (which == 2) v = g_n[r];
    else                 v = g_m[r];
    out[(size_t)M1 * ODIM + i] = v;
}

// ---------------- launch ----------------------------------------------------
extern "C" void kernel_launch(void* const* d_in, const int* in_sizes, int n_in,
                              void* d_out, int out_size) {
    const float* x    = (const float*)d_in[0];
    const float* Wf   = (const float*)d_in[1];
    const float* bf   = (const float*)d_in[2];
    const float* Wi   = (const float*)d_in[3];
    const float* bi   = (const float*)d_in[4];
    const float* Wc   = (const float*)d_in[5];
    const float* bc   = (const float*)d_in[6];
    const float* Wo   = (const float*)d_in[7];
    const float* bo   = (const float*)d_in[8];
    const float* Wout = (const float*)d_in[9];
    const float* bout = (const float*)d_in[10];
    float* out = (float*)d_out;

    static int attr_done = 0;
    if (!attr_done) {
        cudaFuncSetAttribute(k_mma<0>, cudaFuncAttributeMaxDynamicSharedMemorySize, MSMEM_BYTES);
        cudaFuncSetAttribute(k_mma<1>, cudaFuncAttributeMaxDynamicSharedMemorySize, MSMEM_BYTES);
        cudaFuncSetAttribute(k_recur2, cudaFuncAttributeMaxDynamicSharedMemorySize, R2SMEM_BYTES);
        attr_done = 1;
    }

    // prep: split recurrent weights into tf32 hi/lo (blocked layout)
    k_split<<<dim3(4096, 4), 256>>>(Wf, Wi, Wc, Wo);

    // phase 1 (3xTF32 mma.sync): pre[t][g][b][:] = x @ Wg[:I] + bg
    k_mma<0><<<dim3(8, 512, 4), 256, MSMEM_BYTES>>>(
        x, Wf, Wi, Wc, Wo, bf, bi, bc, bo, nullptr);

    // recurrence (3xTF32 mma.sync, persistent, 1 CTA/SM)
    k_recur2<<<REC_BLOCKS, 256, R2SMEM_BYTES>>>();

    // output projection (3xTF32 mma.sync): out = hbuf @ Wout + bout
    k_mma<1><<<dim3(8, 512, 1), 256, MSMEM_BYTES>>>(
        nullptr, Wout, Wout, Wout, Wout, bout, bout, bout, bout, out);

    // final h, c, n, m
    k_tail<<<(4 * BH) / 256, 256>>>(out);
}